// round 1
// baseline (speedup 1.0000x reference)
#include <cuda_runtime.h>
#include <math.h>

#define BB    256
#define HH    128
#define NNODE 1000
#define NPAD  1024
#define K3    384      // adj/static/dyn part of K
#define KB    16       // K-slice per smem stage
#define TILE  128      // output tile: 128 h x 128 n
#define SPAD  132      // padded smem row (floats)

// scratch (allocation-free rule: __device__ globals)
__device__ float g_dvec[BB * HH];        // d[b,h] = W[h,384:512] . dec[b,:]
__device__ float g_attn[BB * NPAD];      // logits, padded row stride

// ---------------------------------------------------------------------------
// Kernel A: d[b,h] bias from the broadcast decoder_hidden quarter
// ---------------------------------------------------------------------------
__global__ void __launch_bounds__(HH) dvec_kernel(const float* __restrict__ dec,
                                                  const float* __restrict__ W)
{
    __shared__ float sdec[HH];
    int b = blockIdx.x;
    int h = threadIdx.x;
    sdec[h] = dec[b * HH + h];
    __syncthreads();
    const float* wrow = W + h * (4 * HH) + 3 * HH;   // W[h, 384:512]
    float s = 0.f;
#pragma unroll 8
    for (int k = 0; k < HH; k++) s += wrow[k] * sdec[k];
    g_dvec[b * HH + h] = s;
}

// ---------------------------------------------------------------------------
// Kernel B: fused scores GEMM + tanh + v-reduction -> logits
//   grid: (8 n-tiles, 256 batches), block: 256 threads (16x16),
//   each thread: 8x8 microtile (rows {ty*4+i, 64+ty*4+i}, cols likewise w/ tx)
// ---------------------------------------------------------------------------
__global__ void __launch_bounds__(256) score_kernel(const float* __restrict__ adj,
                                                    const float* __restrict__ sta,
                                                    const float* __restrict__ dyn,
                                                    const float* __restrict__ W,
                                                    const float* __restrict__ v)
{
    __shared__ float As[KB][SPAD];        // k x h
    __shared__ float Bs[KB][SPAD];        // k x n
    __shared__ float red[16][TILE];       // per-ty partial v-weighted sums

    const int b  = blockIdx.y;
    const int n0 = blockIdx.x * TILE;
    const int tid = threadIdx.x;
    const int tx = tid & 15;              // n group
    const int ty = tid >> 4;              // h group

    float acc[8][8];
#pragma unroll
    for (int i = 0; i < 8; i++)
#pragma unroll
        for (int j = 0; j < 8; j++) acc[i][j] = 0.f;

    // A-load mapping: thread -> (h = tid/4 [0..63], kq = (tid%4)*4), 2 h-halves
    const int a_kq = (tid & 3) * 4;
    const int a_h  = tid >> 2;
    // B-load mapping: thread -> (krow = tid/32 [0..7], nq = (tid%32)*4), 2 k-halves
    const int b_nq = (tid & 31) * 4;
    const int b_kr = tid >> 5;

    for (int k0 = 0; k0 < K3; k0 += KB) {
        // ---- stage A: W[h, k0:k0+16] -> As[k][h]
#pragma unroll
        for (int r = 0; r < 2; r++) {
            int hh = a_h + r * 64;
            float4 w4 = *(const float4*)&W[hh * (4 * HH) + k0 + a_kq];
            As[a_kq + 0][hh] = w4.x;
            As[a_kq + 1][hh] = w4.y;
            As[a_kq + 2][hh] = w4.z;
            As[a_kq + 3][hh] = w4.w;
        }
        // ---- stage B: hidden[b, k0+k, n0:n0+128] -> Bs[k][n]
#pragma unroll
        for (int r = 0; r < 2; r++) {
            int kk = b_kr + r * 8;
            int kg = k0 + kk;
            int sel = kg >> 7;                    // which source array
            const float* src = (sel == 0) ? adj : (sel == 1) ? sta : dyn;
            src += ((size_t)b * HH + (kg & 127)) * NNODE;
            int n = n0 + b_nq;
            float4 val;
            if (n + 3 < NNODE) {
                val = *(const float4*)&src[n];
            } else {
                val.x = (n + 0 < NNODE) ? src[n + 0] : 0.f;
                val.y = (n + 1 < NNODE) ? src[n + 1] : 0.f;
                val.z = (n + 2 < NNODE) ? src[n + 2] : 0.f;
                val.w = (n + 3 < NNODE) ? src[n + 3] : 0.f;
            }
            *(float4*)&Bs[kk][b_nq] = val;
        }
        __syncthreads();

        // ---- compute
#pragma unroll
        for (int kk = 0; kk < KB; kk++) {
            float a[8], bv[8];
            *(float4*)&a[0]  = *(const float4*)&As[kk][ty * 4];
            *(float4*)&a[4]  = *(const float4*)&As[kk][64 + ty * 4];
            *(float4*)&bv[0] = *(const float4*)&Bs[kk][tx * 4];
            *(float4*)&bv[4] = *(const float4*)&Bs[kk][64 + tx * 4];
#pragma unroll
            for (int i = 0; i < 8; i++)
#pragma unroll
                for (int j = 0; j < 8; j++) acc[i][j] += a[i] * bv[j];
        }
        __syncthreads();
    }

    // ---- fused epilogue: + d[b,h], tanh, * v[h], partial-reduce over h
    float colsum[8];
#pragma unroll
    for (int j = 0; j < 8; j++) colsum[j] = 0.f;
#pragma unroll
    for (int i = 0; i < 8; i++) {
        int h = (i < 4) ? (ty * 4 + i) : (64 + ty * 4 + i - 4);
        float dv = g_dvec[b * HH + h];
        float vh = v[h];
#pragma unroll
        for (int j = 0; j < 8; j++)
            colsum[j] += vh * tanhf(acc[i][j] + dv);
    }
#pragma unroll
    for (int j = 0; j < 8; j++) {
        int col = (j < 4) ? (tx * 4 + j) : (64 + tx * 4 + j - 4);
        red[ty][col] = colsum[j];                 // unique (ty,col) per thread... per j
    }
    __syncthreads();
    if (tid < TILE) {
        float s = 0.f;
#pragma unroll
        for (int t = 0; t < 16; t++) s += red[t][tid];
        int n = n0 + tid;
        if (n < NNODE) g_attn[b * NPAD + n] = s;
    }
}

// ---------------------------------------------------------------------------
// Kernel C: row softmax over n (max-sub, two-pass)
// ---------------------------------------------------------------------------
__global__ void __launch_bounds__(256) softmax_kernel(float* __restrict__ out)
{
    __shared__ float sred[256];
    const int b = blockIdx.x;
    const int tid = threadIdx.x;
    const float* row = &g_attn[b * NPAD];

    float m = -INFINITY;
    for (int n = tid; n < NNODE; n += 256) m = fmaxf(m, row[n]);
    sred[tid] = m;
    __syncthreads();
    for (int s = 128; s > 0; s >>= 1) {
        if (tid < s) sred[tid] = fmaxf(sred[tid], sred[tid + s]);
        __syncthreads();
    }
    m = sred[0];
    __syncthreads();

    float sum = 0.f;
    for (int n = tid; n < NNODE; n += 256) sum += __expf(row[n] - m);
    sred[tid] = sum;
    __syncthreads();
    for (int s = 128; s > 0; s >>= 1) {
        if (tid < s) sred[tid] += sred[tid + s];
        __syncthreads();
    }
    float inv = 1.f / sred[0];

    for (int n = tid; n < NNODE; n += 256)
        out[b * NNODE + n] = __expf(row[n] - m) * inv;
}

// ---------------------------------------------------------------------------
extern "C" void kernel_launch(void* const* d_in, const int* in_sizes, int n_in,
                              void* d_out, int out_size)
{
    const float* adj = (const float*)d_in[0];
    const float* sta = (const float*)d_in[1];
    const float* dyn = (const float*)d_in[2];
    const float* dec = (const float*)d_in[3];
    const float* v   = (const float*)d_in[4];
    const float* W   = (const float*)d_in[5];
    float* out = (float*)d_out;

    dvec_kernel<<<BB, HH>>>(dec, W);
    dim3 grid((NPAD + TILE - 1) / TILE, BB);     // (8, 256)
    score_kernel<<<grid, 256>>>(adj, sta, dyn, W, v);
    softmax_kernel<<<BB, 256>>>(out);
}

// round 4
// speedup vs baseline: 1.5093x; 1.5093x over previous
#include <cuda_runtime.h>
#include <cuda_bf16.h>
#include <cstdint>
#include <cstddef>
#include <math.h>

#define BB    256
#define HH    128
#define NNODE 1000
#define NPAD  1024
#define K3    384
#define KC    32          // k per stage (2 x k16 steps)
#define NT    64          // n per CTA
#define APAD  40          // As row stride (bf16 elems)
#define BPAD  72          // Bs row stride (bf16 elems)

// ---------------- scratch (__device__ globals; no allocs allowed) ----------
__device__ float g_dvec[BB * HH];
__device__ float g_attn[BB * NPAD];

// ---------------- helpers --------------------------------------------------
__device__ __forceinline__ uint32_t smem_u32(const void* p) {
    uint32_t a;
    asm("{ .reg .u64 t; cvta.to.shared.u64 t, %1; cvt.u32.u64 %0, t; }" : "=r"(a) : "l"(p));
    return a;
}
__device__ __forceinline__ void ldsm_x4(uint32_t& r0, uint32_t& r1,
                                        uint32_t& r2, uint32_t& r3, uint32_t a) {
    asm volatile("ldmatrix.sync.aligned.m8n8.x4.shared.b16 {%0,%1,%2,%3}, [%4];"
                 : "=r"(r0), "=r"(r1), "=r"(r2), "=r"(r3) : "r"(a));
}
__device__ __forceinline__ void ldsm_x4_t(uint32_t& r0, uint32_t& r1,
                                          uint32_t& r2, uint32_t& r3, uint32_t a) {
    asm volatile("ldmatrix.sync.aligned.m8n8.x4.trans.shared.b16 {%0,%1,%2,%3}, [%4];"
                 : "=r"(r0), "=r"(r1), "=r"(r2), "=r"(r3) : "r"(a));
}
__device__ __forceinline__ void mma16816(float* c, const uint32_t* a,
                                         uint32_t b0, uint32_t b1) {
    asm volatile("mma.sync.aligned.m16n8k16.row.col.f32.bf16.bf16.f32 "
                 "{%0,%1,%2,%3}, {%4,%5,%6,%7}, {%8,%9}, {%0,%1,%2,%3};"
                 : "+f"(c[0]), "+f"(c[1]), "+f"(c[2]), "+f"(c[3])
                 : "r"(a[0]), "r"(a[1]), "r"(a[2]), "r"(a[3]), "r"(b0), "r"(b1));
}
// fp32x4 -> packed bf16x4 hi / lo (residual)
__device__ __forceinline__ void cvt4(float4 f, unsigned long long& hi,
                                     unsigned long long& lo) {
    __nv_bfloat16 h0 = __float2bfloat16(f.x), h1 = __float2bfloat16(f.y);
    __nv_bfloat16 h2 = __float2bfloat16(f.z), h3 = __float2bfloat16(f.w);
    __nv_bfloat16 l0 = __float2bfloat16(f.x - __bfloat162float(h0));
    __nv_bfloat16 l1 = __float2bfloat16(f.y - __bfloat162float(h1));
    __nv_bfloat16 l2 = __float2bfloat16(f.z - __bfloat162float(h2));
    __nv_bfloat16 l3 = __float2bfloat16(f.w - __bfloat162float(h3));
    union { unsigned short s[4]; unsigned long long u; } a, b;
    a.s[0] = __bfloat16_as_ushort(h0); a.s[1] = __bfloat16_as_ushort(h1);
    a.s[2] = __bfloat16_as_ushort(h2); a.s[3] = __bfloat16_as_ushort(h3);
    b.s[0] = __bfloat16_as_ushort(l0); b.s[1] = __bfloat16_as_ushort(l1);
    b.s[2] = __bfloat16_as_ushort(l2); b.s[3] = __bfloat16_as_ushort(l3);
    hi = a.u; lo = b.u;
}

// ---------------------------------------------------------------------------
// Kernel A: d[b,h] = W[h,384:512] . dec[b,:]
// ---------------------------------------------------------------------------
__global__ void __launch_bounds__(HH) dvec_kernel(const float* __restrict__ dec,
                                                  const float* __restrict__ W)
{
    __shared__ float4 sdec[HH / 4];
    int b = blockIdx.x, h = threadIdx.x;
    if (h < HH / 4) sdec[h] = *(const float4*)&dec[b * HH + h * 4];
    __syncthreads();
    const float4* w4 = (const float4*)(W + h * (4 * HH) + 3 * HH);
    float s0 = 0.f, s1 = 0.f, s2 = 0.f, s3 = 0.f;
#pragma unroll 8
    for (int i = 0; i < 32; i++) {
        float4 wv = w4[i];
        float4 dv = sdec[i];
        s0 += wv.x * dv.x; s1 += wv.y * dv.y;
        s2 += wv.z * dv.z; s3 += wv.w * dv.w;
    }
    g_dvec[b * HH + h] = (s0 + s1) + (s2 + s3);
}

// ---------------------------------------------------------------------------
// Kernel B: HMMA bf16-split GEMM + fused tanh/v epilogue
//   grid (16 n-tiles, 256 b), 256 threads = 8 warps (4 in h, 2 in n)
// ---------------------------------------------------------------------------
__global__ void __launch_bounds__(256, 2)
score_kernel(const float* __restrict__ adj,
             const float* __restrict__ sta,
             const float* __restrict__ dyn,
             const float* __restrict__ W,
             const float* __restrict__ v)
{
    __shared__ __nv_bfloat16 As_hi[HH * APAD];   // 128 h x 32 k (padded)
    __shared__ __nv_bfloat16 As_lo[HH * APAD];
    __shared__ __nv_bfloat16 Bs_hi[KC * BPAD];   // 32 k x 64 n (padded)
    __shared__ __nv_bfloat16 Bs_lo[KC * BPAD];
    __shared__ float red[4][NT];                 // cross-warp h reduction

    const int tid = threadIdx.x;
    const int lane = tid & 31;
    const int wrp  = tid >> 5;
    const int wm   = wrp >> 1;       // 0..3 (h quarter)
    const int wn   = wrp & 1;        // 0..1 (n half)
    const int b  = blockIdx.y;
    const int n0 = blockIdx.x * NT;

    const float* srcs[3] = {
        adj + (size_t)b * HH * NNODE,
        sta + (size_t)b * HH * NNODE,
        dyn + (size_t)b * HH * NNODE };

    float acc[2][4][4];              // [mt][nt][c]
#pragma unroll
    for (int mt = 0; mt < 2; mt++)
#pragma unroll
        for (int nt = 0; nt < 4; nt++)
#pragma unroll
            for (int c = 0; c < 4; c++) acc[mt][nt][c] = 0.f;

    // per-lane ldmatrix smem addresses (bytes)
    const uint32_t aBaseHi = smem_u32(As_hi);
    const uint32_t aBaseLo = smem_u32(As_lo);
    const uint32_t bBaseHi = smem_u32(Bs_hi);
    const uint32_t bBaseLo = smem_u32(Bs_lo);
    const int aRow = wm * 32 + (lane & 15);        // + mt*16
    const int aCol = (lane >> 4) * 8;              // + ks*16
    const int bRow = (lane & 15);                  // + ks*16
    const int bCol = wn * 32 + (lane >> 4) * 8;    // + ntg*16

    for (int it = 0; it < K3 / KC; it++) {
        const int k0 = it * KC;
        __syncthreads();   // previous compute done before overwriting smem

        // ---- stage A: W[h][k0..k0+31] (4 float4 per thread)
#pragma unroll
        for (int i = 0; i < 4; i++) {
            int idx = tid + i * 256;
            int row = idx >> 3, q = idx & 7;
            float4 f = *(const float4*)&W[row * (4 * HH) + k0 + q * 4];
            unsigned long long hi, lo;
            cvt4(f, hi, lo);
            *(unsigned long long*)&As_hi[row * APAD + q * 4] = hi;
            *(unsigned long long*)&As_lo[row * APAD + q * 4] = lo;
        }
        // ---- stage B: hidden[b][k0+k][n0..n0+63] (2 float4 per thread)
#pragma unroll
        for (int i = 0; i < 2; i++) {
            int idx = tid + i * 256;
            int krow = idx >> 4, q = idx & 15;
            int kg = k0 + krow;
            const float* src = srcs[kg >> 7] + (size_t)(kg & 127) * NNODE;
            int n = n0 + q * 4;
            float4 f = (n + 3 < NNODE) ? *(const float4*)&src[n]
                                       : make_float4((n+0<NNODE)?src[n+0]:0.f,
                                                     (n+1<NNODE)?src[n+1]:0.f,
                                                     (n+2<NNODE)?src[n+2]:0.f,
                                                     (n+3<NNODE)?src[n+3]:0.f);
            unsigned long long hi, lo;
            cvt4(f, hi, lo);
            *(unsigned long long*)&Bs_hi[krow * BPAD + q * 4] = hi;
            *(unsigned long long*)&Bs_lo[krow * BPAD + q * 4] = lo;
        }
        __syncthreads();

        // ---- compute: 2 k16 steps
#pragma unroll
        for (int ks = 0; ks < 2; ks++) {
            uint32_t ah[2][4], al[2][4];
#pragma unroll
            for (int mt = 0; mt < 2; mt++) {
                uint32_t off = (uint32_t)(((aRow + mt * 16) * APAD + ks * 16 + aCol) * 2);
                ldsm_x4(ah[mt][0], ah[mt][1], ah[mt][2], ah[mt][3], aBaseHi + off);
                ldsm_x4(al[mt][0], al[mt][1], al[mt][2], al[mt][3], aBaseLo + off);
            }
            uint32_t bh[8], bl[8];    // [nt*2 + reg]
#pragma unroll
            for (int ntg = 0; ntg < 2; ntg++) {
                uint32_t off = (uint32_t)(((ks * 16 + bRow) * BPAD + bCol + ntg * 16) * 2);
                ldsm_x4_t(bh[ntg*4+0], bh[ntg*4+1], bh[ntg*4+2], bh[ntg*4+3], bBaseHi + off);
                ldsm_x4_t(bl[ntg*4+0], bl[ntg*4+1], bl[ntg*4+2], bl[ntg*4+3], bBaseLo + off);
            }
#pragma unroll
            for (int mt = 0; mt < 2; mt++)
#pragma unroll
                for (int nt = 0; nt < 4; nt++) {
                    uint32_t b0h = bh[nt*2+0], b1h = bh[nt*2+1];
                    uint32_t b0l = bl[nt*2+0], b1l = bl[nt*2+1];
                    mma16816(acc[mt][nt], ah[mt], b0h, b1h);   // hi*hi
                    mma16816(acc[mt][nt], al[mt], b0h, b1h);   // lo*hi
                    mma16816(acc[mt][nt], ah[mt], b0l, b1l);   // hi*lo
                }
        }
    }

    // ---- epilogue: tanh(acc + d) * v, reduce over h
    const int g = lane >> 2, t = lane & 3;
    const float* dp = g_dvec + b * HH;
    float d0[2], d1[2], v0[2], v1[2];
#pragma unroll
    for (int mt = 0; mt < 2; mt++) {
        int h0 = wm * 32 + mt * 16 + g;
        d0[mt] = dp[h0];     d1[mt] = dp[h0 + 8];
        v0[mt] = v[h0];      v1[mt] = v[h0 + 8];
    }
    float p[4][2];
#pragma unroll
    for (int nt = 0; nt < 4; nt++)
#pragma unroll
        for (int c = 0; c < 2; c++) {
            float s = 0.f;
#pragma unroll
            for (int mt = 0; mt < 2; mt++)
                s += v0[mt] * tanhf(acc[mt][nt][c]     + d0[mt])
                   + v1[mt] * tanhf(acc[mt][nt][c + 2] + d1[mt]);
            p[nt][c] = s;
        }
    // reduce over g (lanes stride 4)
#pragma unroll
    for (int m = 4; m <= 16; m <<= 1)
#pragma unroll
        for (int nt = 0; nt < 4; nt++)
#pragma unroll
            for (int c = 0; c < 2; c++)
                p[nt][c] += __shfl_xor_sync(0xFFFFFFFFu, p[nt][c], m);
    if (g == 0) {
#pragma unroll
        for (int nt = 0; nt < 4; nt++)
#pragma unroll
            for (int c = 0; c < 2; c++)
                red[wm][wn * 32 + nt * 8 + t * 2 + c] = p[nt][c];
    }
    __syncthreads();
    if (tid < NT) {
        float s = red[0][tid] + red[1][tid] + red[2][tid] + red[3][tid];
        int n = n0 + tid;
        if (n < NNODE) g_attn[b * NPAD + n] = s;
    }
}

// ---------------------------------------------------------------------------
// Kernel C: row softmax
// ---------------------------------------------------------------------------
__global__ void __launch_bounds__(256) softmax_kernel(float* __restrict__ out)
{
    __shared__ float sred[256];
    const int b = blockIdx.x, tid = threadIdx.x;
    const float* row = &g_attn[b * NPAD];

    float m = -INFINITY;
    for (int n = tid; n < NNODE; n += 256) m = fmaxf(m, row[n]);
    sred[tid] = m;  __syncthreads();
    for (int s = 128; s > 0; s >>= 1) {
        if (tid < s) sred[tid] = fmaxf(sred[tid], sred[tid + s]);
        __syncthreads();
    }
    m = sred[0];  __syncthreads();

    float sum = 0.f;
    for (int n = tid; n < NNODE; n += 256) sum += __expf(row[n] - m);
    sred[tid] = sum;  __syncthreads();
    for (int s = 128; s > 0; s >>= 1) {
        if (tid < s) sred[tid] += sred[tid + s];
        __syncthreads();
    }
    float inv = 1.f / sred[0];

    for (int n = tid; n < NNODE; n += 256)
        out[b * NNODE + n] = __expf(row[n] - m) * inv;
}

// ---------------------------------------------------------------------------
extern "C" void kernel_launch(void* const* d_in, const int* in_sizes, int n_in,
                              void* d_out, int out_size)
{
    const float* adj = (const float*)d_in[0];
    const float* sta = (const float*)d_in[1];
    const float* dyn = (const float*)d_in[2];
    const float* dec = (const float*)d_in[3];
    const float* v   = (const float*)d_in[4];
    const float* W   = (const float*)d_in[5];
    float* out = (float*)d_out;

    dvec_kernel<<<BB, HH>>>(dec, W);
    dim3 grid(NPAD / NT, BB);                    // (16, 256)
    score_kernel<<<grid, 256>>>(adj, sta, dyn, W, v);
    softmax_kernel<<<BB, 256>>>(out);
}

// round 6
// speedup vs baseline: 2.3958x; 1.5874x over previous
#include <cuda_runtime.h>
#include <cuda_bf16.h>
#include <cstdint>
#include <cstddef>
#include <math.h>

#define BB    256
#define HH    128
#define NNODE 1000
#define NPAD  1024
#define K3    384
#define KC    32          // k per stage (2 x k16 steps)
#define NT    64          // n per CTA
#define APAD  40          // As row stride (bf16)
#define BPAD  72          // Bs row stride (bf16)
#define BFW   64          // B fp32 staging row stride (floats)

// ---------------- scratch (__device__ globals) -----------------------------
__device__ float g_dvec[BB * HH];
__device__ float g_attn[BB * NPAD];
__device__ __nv_bfloat16 g_whi[HH * K3];
__device__ __nv_bfloat16 g_wlo[HH * K3];

// ---------------- helpers --------------------------------------------------
__device__ __forceinline__ uint32_t smem_u32(const void* p) {
    uint32_t a;
    asm("{ .reg .u64 t; cvta.to.shared.u64 t, %1; cvt.u32.u64 %0, t; }" : "=r"(a) : "l"(p));
    return a;
}
#define CP16(dst, src) \
    asm volatile("cp.async.cg.shared.global [%0], [%1], 16;" :: "r"(dst), "l"(src))
#define CP16Z(dst, src, nb) \
    asm volatile("cp.async.cg.shared.global [%0], [%1], 16, %2;" :: "r"(dst), "l"(src), "r"(nb))
#define CP_COMMIT() asm volatile("cp.async.commit_group;")
#define CP_WAIT(n)  asm volatile("cp.async.wait_group %0;" :: "n"(n))

__device__ __forceinline__ void ldsm_x4(uint32_t& r0, uint32_t& r1,
                                        uint32_t& r2, uint32_t& r3, uint32_t a) {
    asm volatile("ldmatrix.sync.aligned.m8n8.x4.shared.b16 {%0,%1,%2,%3}, [%4];"
                 : "=r"(r0), "=r"(r1), "=r"(r2), "=r"(r3) : "r"(a));
}
__device__ __forceinline__ void ldsm_x4_t(uint32_t& r0, uint32_t& r1,
                                          uint32_t& r2, uint32_t& r3, uint32_t a) {
    asm volatile("ldmatrix.sync.aligned.m8n8.x4.trans.shared.b16 {%0,%1,%2,%3}, [%4];"
                 : "=r"(r0), "=r"(r1), "=r"(r2), "=r"(r3) : "r"(a));
}
__device__ __forceinline__ void mma16816(float* c, const uint32_t* a,
                                         uint32_t b0, uint32_t b1) {
    asm volatile("mma.sync.aligned.m16n8k16.row.col.f32.bf16.bf16.f32 "
                 "{%0,%1,%2,%3}, {%4,%5,%6,%7}, {%8,%9}, {%0,%1,%2,%3};"
                 : "+f"(c[0]), "+f"(c[1]), "+f"(c[2]), "+f"(c[3])
                 : "r"(a[0]), "r"(a[1]), "r"(a[2]), "r"(a[3]), "r"(b0), "r"(b1));
}
__device__ __forceinline__ void cvt4(float4 f, unsigned long long& hi,
                                     unsigned long long& lo) {
    __nv_bfloat16 h0 = __float2bfloat16(f.x), h1 = __float2bfloat16(f.y);
    __nv_bfloat16 h2 = __float2bfloat16(f.z), h3 = __float2bfloat16(f.w);
    __nv_bfloat16 l0 = __float2bfloat16(f.x - __bfloat162float(h0));
    __nv_bfloat16 l1 = __float2bfloat16(f.y - __bfloat162float(h1));
    __nv_bfloat16 l2 = __float2bfloat16(f.z - __bfloat162float(h2));
    __nv_bfloat16 l3 = __float2bfloat16(f.w - __bfloat162float(h3));
    union { unsigned short s[4]; unsigned long long u; } a, b;
    a.s[0] = __bfloat16_as_ushort(h0); a.s[1] = __bfloat16_as_ushort(h1);
    a.s[2] = __bfloat16_as_ushort(h2); a.s[3] = __bfloat16_as_ushort(h3);
    b.s[0] = __bfloat16_as_ushort(l0); b.s[1] = __bfloat16_as_ushort(l1);
    b.s[2] = __bfloat16_as_ushort(l2); b.s[3] = __bfloat16_as_ushort(l3);
    hi = a.u; lo = b.u;
}
__device__ __forceinline__ float tanh_fast(float x) {
    float t = __expf(2.f * x);
    return 1.f - __fdividef(2.f, t + 1.f);
}

// SMEM layout (bytes)
#define SO_AHI  0                                   // 2 x 128*APAD bf16
#define SO_ALO  (SO_AHI + 2 * HH * APAD * 2)        // 20480
#define SO_BF   (SO_ALO + 2 * HH * APAD * 2)        // 40960: 2 x 32*BFW fp32
#define SO_BSH  (SO_BF + 2 * KC * BFW * 4)          // 57344: 32*BPAD bf16
#define SO_BSL  (SO_BSH + KC * BPAD * 2)            // 61952
#define SO_RED  (SO_BSL + KC * BPAD * 2)            // 66560: 4*64 fp32
#define SMEM_SZ (SO_RED + 4 * NT * 4)               // 67584

// ---------------------------------------------------------------------------
// Kernel W-pack: W[:, :384] -> bf16 hi/lo
// ---------------------------------------------------------------------------
__global__ void __launch_bounds__(96) wpack_kernel(const float* __restrict__ W)
{
    int h = blockIdx.x, k = threadIdx.x * 4;
    float4 f = *(const float4*)&W[h * (4 * HH) + k];
    unsigned long long hi, lo;
    cvt4(f, hi, lo);
    *(unsigned long long*)&g_whi[h * K3 + k] = hi;
    *(unsigned long long*)&g_wlo[h * K3 + k] = lo;
}

// ---------------------------------------------------------------------------
// Kernel A: d[b,h] = W[h,384:512] . dec[b,:]
// ---------------------------------------------------------------------------
__global__ void __launch_bounds__(HH) dvec_kernel(const float* __restrict__ dec,
                                                  const float* __restrict__ W)
{
    __shared__ float4 sdec[HH / 4];
    int b = blockIdx.x, h = threadIdx.x;
    if (h < HH / 4) sdec[h] = *(const float4*)&dec[b * HH + h * 4];
    __syncthreads();
    const float4* w4 = (const float4*)(W + h * (4 * HH) + 3 * HH);
    float s0 = 0.f, s1 = 0.f, s2 = 0.f, s3 = 0.f;
#pragma unroll 8
    for (int i = 0; i < 32; i++) {
        float4 wv = w4[i];
        float4 dv = sdec[i];
        s0 += wv.x * dv.x; s1 += wv.y * dv.y;
        s2 += wv.z * dv.z; s3 += wv.w * dv.w;
    }
    g_dvec[b * HH + h] = (s0 + s1) + (s2 + s3);
}

// ---------------------------------------------------------------------------
// Kernel B: pipelined HMMA bf16-split GEMM + fused tanh/v epilogue
// ---------------------------------------------------------------------------
__global__ void __launch_bounds__(256, 2)
score_kernel(const float* __restrict__ adj,
             const float* __restrict__ sta,
             const float* __restrict__ dyn,
             const float* __restrict__ v)
{
    extern __shared__ __align__(16) char smem[];
    __nv_bfloat16* As_hi = (__nv_bfloat16*)(smem + SO_AHI);
    __nv_bfloat16* As_lo = (__nv_bfloat16*)(smem + SO_ALO);
    float*         Bf    = (float*)(smem + SO_BF);
    __nv_bfloat16* Bs_hi = (__nv_bfloat16*)(smem + SO_BSH);
    __nv_bfloat16* Bs_lo = (__nv_bfloat16*)(smem + SO_BSL);
    float*         red   = (float*)(smem + SO_RED);

    const int tid  = threadIdx.x;
    const int lane = tid & 31;
    const int wrp  = tid >> 5;
    const int wm   = wrp >> 1;       // 0..3 (h quarter)
    const int wn   = wrp & 1;        // 0..1 (n half)
    const int b  = blockIdx.y;
    const int n0 = blockIdx.x * NT;

    const float* srcs[3] = {
        adj + (size_t)b * HH * NNODE,
        sta + (size_t)b * HH * NNODE,
        dyn + (size_t)b * HH * NNODE };

    const uint32_t uAhi = smem_u32(As_hi), uAlo = smem_u32(As_lo);
    const uint32_t uBf  = smem_u32(Bf);
    auto stage = [&](int it, int s) {
        const int k0 = it * KC;
        // A: g_whi/g_wlo[h][k0..k0+31], 16B chunks (8 bf16)
#pragma unroll
        for (int i = 0; i < 2; i++) {
            int idx = tid + i * 256;
            int row = idx >> 2, q = idx & 3;
            uint32_t doff = (uint32_t)((s * HH * APAD + row * APAD + q * 8) * 2);
            const __nv_bfloat16* sh = &g_whi[row * K3 + k0 + q * 8];
            const __nv_bfloat16* sl = &g_wlo[row * K3 + k0 + q * 8];
            CP16(uAhi + doff, sh);
            CP16(uAlo + doff, sl);
        }
        // B: hidden[b][k0+k][n0..n0+63] fp32, 16B chunks (4 floats), zero-fill OOB
#pragma unroll
        for (int i = 0; i < 2; i++) {
            int idx = tid + i * 256;
            int krow = idx >> 4, q = idx & 15;
            int kg = k0 + krow;
            const float* src = srcs[kg >> 7] + (size_t)(kg & 127) * NNODE + n0 + q * 4;
            uint32_t doff = (uint32_t)((s * KC * BFW + krow * BFW + q * 4) * 4);
            uint32_t nb = (n0 + q * 4 < NNODE) ? 16u : 0u;
            CP16Z(uBf + doff, src, nb);
        }
        CP_COMMIT();
    };

    float acc[2][4][4];
#pragma unroll
    for (int mt = 0; mt < 2; mt++)
#pragma unroll
        for (int nt = 0; nt < 4; nt++)
#pragma unroll
            for (int c = 0; c < 4; c++) acc[mt][nt][c] = 0.f;

    const uint32_t bshU = smem_u32(Bs_hi), bslU = smem_u32(Bs_lo);
    const int aRow = wm * 32 + (lane & 15);        // + mt*16
    const int aCol = (lane >> 4) * 8;              // + ks*16
    const int bRow = (lane & 15);                  // + ks*16
    const int bCol = wn * 32 + (lane >> 4) * 8;    // + ntg*16

    stage(0, 0);                                    // prologue

    const int NCH = K3 / KC;                        // 12
    for (int it = 0; it < NCH; it++) {
        const int s = it & 1;
        // BARRIER 1: all warps finished previous compute (reads of As[s^1], Bs)
        // before anyone overwrites As[s^1]/Bf[s^1] with cp.async.
        __syncthreads();
        if (it + 1 < NCH) { stage(it + 1, s ^ 1); CP_WAIT(1); }
        else              { CP_WAIT(0); }
        // BARRIER 2: stage `s` cp.async data visible to every warp.
        __syncthreads();

        // ---- convert B fp32 staging -> bf16 hi/lo
#pragma unroll
        for (int i = 0; i < 2; i++) {
            int idx = tid + i * 256;
            int krow = idx >> 4, q = idx & 15;
            float4 f = *(float4*)&Bf[s * KC * BFW + krow * BFW + q * 4];
            unsigned long long hi, lo;
            cvt4(f, hi, lo);
            *(unsigned long long*)&Bs_hi[krow * BPAD + q * 4] = hi;
            *(unsigned long long*)&Bs_lo[krow * BPAD + q * 4] = lo;
        }
        // BARRIER 3: Bs ready for ldmatrix.
        __syncthreads();

        // ---- compute: 2 k16 steps
        const uint32_t aOffS = (uint32_t)(s * HH * APAD * 2);
#pragma unroll
        for (int ks = 0; ks < 2; ks++) {
            uint32_t ah[2][4], al[2][4];
#pragma unroll
            for (int mt = 0; mt < 2; mt++) {
                uint32_t off = aOffS + (uint32_t)(((aRow + mt * 16) * APAD + ks * 16 + aCol) * 2);
                ldsm_x4(ah[mt][0], ah[mt][1], ah[mt][2], ah[mt][3], uAhi + off);
                ldsm_x4(al[mt][0], al[mt][1], al[mt][2], al[mt][3], uAlo + off);
            }
            uint32_t bh[8], bl[8];
#pragma unroll
            for (int ntg = 0; ntg < 2; ntg++) {
                uint32_t off = (uint32_t)(((ks * 16 + bRow) * BPAD + bCol + ntg * 16) * 2);
                ldsm_x4_t(bh[ntg*4+0], bh[ntg*4+1], bh[ntg*4+2], bh[ntg*4+3], bshU + off);
                ldsm_x4_t(bl[ntg*4+0], bl[ntg*4+1], bl[ntg*4+2], bl[ntg*4+3], bslU + off);
            }
#pragma unroll
            for (int mt = 0; mt < 2; mt++)
#pragma unroll
                for (int nt = 0; nt < 4; nt++) {
                    uint32_t b0h = bh[nt*2+0], b1h = bh[nt*2+1];
                    uint32_t b0l = bl[nt*2+0], b1l = bl[nt*2+1];
                    mma16816(acc[mt][nt], ah[mt], b0h, b1h);   // hi*hi
                    mma16816(acc[mt][nt], al[mt], b0h, b1h);   // lo*hi
                    mma16816(acc[mt][nt], ah[mt], b0l, b1l);   // hi*lo
                }
        }
    }

    // ---- epilogue: tanh(acc + d) * v, reduce over h
    const int g = lane >> 2, t = lane & 3;
    const float* dp = g_dvec + b * HH;
    float d0[2], d1[2], v0[2], v1[2];
#pragma unroll
    for (int mt = 0; mt < 2; mt++) {
        int h0 = wm * 32 + mt * 16 + g;
        d0[mt] = dp[h0];     d1[mt] = dp[h0 + 8];
        v0[mt] = v[h0];      v1[mt] = v[h0 + 8];
    }
    float p[4][2];
#pragma unroll
    for (int nt = 0; nt < 4; nt++)
#pragma unroll
        for (int c = 0; c < 2; c++) {
            float sacc = 0.f;
#pragma unroll
            for (int mt = 0; mt < 2; mt++)
                sacc += v0[mt] * tanh_fast(acc[mt][nt][c]     + d0[mt])
                      + v1[mt] * tanh_fast(acc[mt][nt][c + 2] + d1[mt]);
            p[nt][c] = sacc;
        }
#pragma unroll
    for (int m = 4; m <= 16; m <<= 1)
#pragma unroll
        for (int nt = 0; nt < 4; nt++)
#pragma unroll
            for (int c = 0; c < 2; c++)
                p[nt][c] += __shfl_xor_sync(0xFFFFFFFFu, p[nt][c], m);
    if (g == 0) {
#pragma unroll
        for (int nt = 0; nt < 4; nt++)
#pragma unroll
            for (int c = 0; c < 2; c++)
                red[wm * NT + wn * 32 + nt * 8 + t * 2 + c] = p[nt][c];
    }
    __syncthreads();
    if (tid < NT) {
        float sacc = red[0*NT+tid] + red[1*NT+tid] + red[2*NT+tid] + red[3*NT+tid];
        int n = n0 + tid;
        if (n < NNODE) g_attn[b * NPAD + n] = sacc;
    }
}

// ---------------------------------------------------------------------------
// Kernel C: row softmax
// ---------------------------------------------------------------------------
__global__ void __launch_bounds__(256) softmax_kernel(float* __restrict__ out)
{
    __shared__ float sred[256];
    const int b = blockIdx.x, tid = threadIdx.x;
    const float* row = &g_attn[b * NPAD];

    float m = -INFINITY;
    for (int n = tid; n < NNODE; n += 256) m = fmaxf(m, row[n]);
    sred[tid] = m;  __syncthreads();
    for (int s = 128; s > 0; s >>= 1) {
        if (tid < s) sred[tid] = fmaxf(sred[tid], sred[tid + s]);
        __syncthreads();
    }
    m = sred[0];  __syncthreads();

    float sum = 0.f;
    for (int n = tid; n < NNODE; n += 256) sum += __expf(row[n] - m);
    sred[tid] = sum;  __syncthreads();
    for (int s = 128; s > 0; s >>= 1) {
        if (tid < s) sred[tid] += sred[tid + s];
        __syncthreads();
    }
    float inv = 1.f / sred[0];

    for (int n = tid; n < NNODE; n += 256)
        out[b * NNODE + n] = __expf(row[n] - m) * inv;
}

// ---------------------------------------------------------------------------
extern "C" void kernel_launch(void* const* d_in, const int* in_sizes, int n_in,
                              void* d_out, int out_size)
{
    const float* adj = (const float*)d_in[0];
    const float* sta = (const float*)d_in[1];
    const float* dyn = (const float*)d_in[2];
    const float* dec = (const float*)d_in[3];
    const float* v   = (const float*)d_in[4];
    const float* W   = (const float*)d_in[5];
    float* out = (float*)d_out;

    cudaFuncSetAttribute(score_kernel,
                         cudaFuncAttributeMaxDynamicSharedMemorySize, SMEM_SZ);

    wpack_kernel<<<HH, 96>>>(W);
    dvec_kernel<<<BB, HH>>>(dec, W);
    dim3 grid(NPAD / NT, BB);                    // (16, 256)
    score_kernel<<<grid, 256, SMEM_SZ>>>(adj, sta, dyn, v);
    softmax_kernel<<<BB, 256>>>(out);
}